// round 12
// baseline (speedup 1.0000x reference)
#include <cuda_runtime.h>
#include <cuda_bf16.h>

// Fixed shapes per reference setup_inputs
#define BB 8
#define CC 3
#define HH 224
#define WW 224
#define NPIX (HH * WW)          // 50176
#define NSEG 196
#define EE 768
#define NROWS (BB * NSEG)       // 1568
#define ACC_STRIDE 64           // 64 floats = 256 B per (rep,row); 6 used
#define NREP 4                  // accumulator replicas

#define NBLOCKS 392             // 100352 4-px groups / 256; also NROWS/4 rows
#define NTHREADS 384            // 256 scatter threads; 2x192 projection slots

// Scratch: 4 reps * 1568 rows * 256 B = 1.6 MB. Zero at module load; the
// projection phase re-zeroes every word it consumes each launch.
__device__ float g_acc[(long)NREP * NROWS * ACC_STRIDE];
// Monotone ticket counter: never reset. Each launch consumes exactly 392
// tickets, so target = old - old%392 + 392 is launch-local and deterministic.
__device__ unsigned int g_ctr;

// ---------------------------------------------------------------------------
__device__ __forceinline__ void red_add_v4(float* addr, float a, float b,
                                           float c, float d) {
    asm volatile("red.global.add.v4.f32 [%0], {%1, %2, %3, %4};"
                 :: "l"(addr), "f"(a), "f"(b), "f"(c), "f"(d) : "memory");
}
__device__ __forceinline__ void red_add_v2(float* addr, float a, float b) {
    asm volatile("red.global.add.v2.f32 [%0], {%1, %2};"
                 :: "l"(addr), "f"(a), "f"(b) : "memory");
}
__device__ __forceinline__ float ld_cg(const float* p) {
    float v;
    asm volatile("ld.global.cg.f32 %0, [%1];" : "=f"(v) : "l"(p));
    return v;
}
__device__ __forceinline__ unsigned int ld_acquire_gpu(const unsigned int* p) {
    unsigned int v;
    asm volatile("ld.global.acquire.gpu.u32 %0, [%1];" : "=r"(v) : "l"(p));
    return v;
}

// ---------------------------------------------------------------------------
// Single fused kernel.
// ---------------------------------------------------------------------------
__global__ void __launch_bounds__(NTHREADS, 3)
fused_kernel(const float* __restrict__ img,
             const int* __restrict__ seg,
             const float* __restrict__ Wm,
             const float* __restrict__ bias,
             float* __restrict__ out) {
    __shared__ float wsm[5 * EE + EE];     // W (5x768) then bias (768): 21KB
    __shared__ float raw[4][NREP][6];
    __shared__ float sums[4][6];

    const int tid = threadIdx.x;

    // ------------- Phase A: scatter (threads 0-255) -------------
    if (tid < 256) {
        int t  = blockIdx.x * 256 + tid;            // one 4-pixel group
        int b  = t / (NPIX / 4);
        int n4 = t - b * (NPIX / 4);
        int n  = n4 * 4;
        int h  = n / WW;
        int w  = n - h * WW;

        const float4 r4 = *reinterpret_cast<const float4*>(img + ((long)(b * CC + 0) * NPIX + n));
        const float4 g4 = *reinterpret_cast<const float4*>(img + ((long)(b * CC + 1) * NPIX + n));
        const float4 b4 = *reinterpret_cast<const float4*>(img + ((long)(b * CC + 2) * NPIX + n));
        const int4   s4 = *reinterpret_cast<const int4*>(seg + (long)b * NPIX + n);

        const float inv = 1.0f / 223.0f;
        float y = (float)h * inv;

        float rr[4] = {r4.x, r4.y, r4.z, r4.w};
        float gg[4] = {g4.x, g4.y, g4.z, g4.w};
        float bb[4] = {b4.x, b4.y, b4.z, b4.w};
        int   ss[4] = {s4.x, s4.y, s4.z, s4.w};

        float* rep = g_acc + (long)(blockIdx.x & (NREP - 1)) * ((long)NROWS * ACC_STRIDE);

#pragma unroll
        for (int i = 0; i < 4; i++) {
            float x = (float)(w + i) * inv;
            float* base = rep + (long)(b * NSEG + ss[i]) * ACC_STRIDE;
            red_add_v4(base, rr[i], gg[i], bb[i], x);
            red_add_v2(base + 4, y, 1.0f);
        }
    }

    // ------------- Stage W + bias into smem (all threads, pre-barrier) -----
    {
        float4* dst = reinterpret_cast<float4*>(wsm);
        const float4* srcW = reinterpret_cast<const float4*>(Wm);
        const float4* srcB = reinterpret_cast<const float4*>(bias);
#pragma unroll
        for (int k = 0; k < 3; k++) {               // 1152 float4 / 384 thr
            int i = tid + k * NTHREADS;
            dst[i] = (i < 960) ? srcW[i] : srcB[i - 960];
        }
    }

    // ------------- Grid barrier (ticket, monotone counter) -----------------
    __threadfence();                                // commit this block's REDs
    __syncthreads();                                // all threads fenced
    if (tid == 0) {
        unsigned int old = atomicAdd(&g_ctr, 1u);
        unsigned int target = old - (old % (unsigned)NBLOCKS) + (unsigned)NBLOCKS;
        while ((int)(ld_acquire_gpu(&g_ctr) - target) < 0) { }
    }
    __syncthreads();

    // ------------- Phase B: projection (4 rows per block) ------------------
    const int row0 = blockIdx.x * 4;

    if (tid < 96) {
        int row = tid / 24;
        int l   = tid - row * 24;
        int rep = l / 6;
        int j   = l - rep * 6;
        float* p = g_acc + (long)rep * ((long)NROWS * ACC_STRIDE)
                         + (long)(row0 + row) * ACC_STRIDE + j;
        float v = ld_cg(p);
        *p = 0.0f;                                  // reset for next replay
        raw[row][rep][j] = v;
    }
    __syncthreads();

    if (tid < 24) {
        int row = tid / 6;
        int j   = tid - row * 6;
        sums[row][j] = raw[row][0][j] + raw[row][1][j]
                     + raw[row][2][j] + raw[row][3][j];
    }
    __syncthreads();

    const int slot = tid / 192;                     // 0 or 1
    const int t    = tid - slot * 192;              // 0..191
    const int e    = t * 4;                         // 0..764

    const float4* wsm4 = reinterpret_cast<const float4*>(wsm);
    float4 w0 = wsm4[0 * 192 + t];
    float4 w1 = wsm4[1 * 192 + t];
    float4 w2 = wsm4[2 * 192 + t];
    float4 w3 = wsm4[3 * 192 + t];
    float4 w4 = wsm4[4 * 192 + t];
    float4 bv = wsm4[5 * 192 + t];

#pragma unroll
    for (int rr = 0; rr < 2; rr++) {
        int row = slot * 2 + rr;
        float cnt = sums[row][5];
        bool  empty = !(cnt > 0.0f);
        float invc  = empty ? 0.0f : (1.0f / cnt);

        float m0 = sums[row][0] * invc;
        float m1 = sums[row][1] * invc;
        float m2 = sums[row][2] * invc;
        float m3 = sums[row][3] * invc;
        float m4 = sums[row][4] * invc;

        float4 r;
        r.x = m0 * w0.x + m1 * w1.x + m2 * w2.x + m3 * w3.x + m4 * w4.x + bv.x;
        r.y = m0 * w0.y + m1 * w1.y + m2 * w2.y + m3 * w3.y + m4 * w4.y + bv.y;
        r.z = m0 * w0.z + m1 * w1.z + m2 * w2.z + m3 * w3.z + m4 * w4.z + bv.z;
        r.w = m0 * w0.w + m1 * w1.w + m2 * w2.w + m3 * w3.w + m4 * w4.w + bv.w;
        if (empty) r = make_float4(0.f, 0.f, 0.f, 0.f);

        *reinterpret_cast<float4*>(out + (long)(row0 + row) * EE + e) = r;
    }
}

// ---------------------------------------------------------------------------
extern "C" void kernel_launch(void* const* d_in, const int* in_sizes, int n_in,
                              void* d_out, int out_size) {
    const float* img  = (const float*)d_in[0];   // [8,3,224,224]
    const int*   seg  = (const int*)d_in[1];     // [8,224,224]
    const float* Wm   = (const float*)d_in[2];   // [5,768]
    const float* bias = (const float*)d_in[3];   // [768]
    float* out = (float*)d_out;                  // [8,196,768]

    (void)in_sizes; (void)n_in; (void)out_size;

    fused_kernel<<<NBLOCKS, NTHREADS>>>(img, seg, Wm, bias, out);
}

// round 13
// speedup vs baseline: 1.1380x; 1.1380x over previous
#include <cuda_runtime.h>
#include <cuda_bf16.h>

// Fixed shapes per reference setup_inputs
#define BB 8
#define CC 3
#define HH 224
#define WW 224
#define NPIX (HH * WW)          // 50176
#define NSEG 196
#define EE 768
#define NROWS (BB * NSEG)       // 1568
#define ACC_STRIDE 64           // 64 floats = 256 B per (rep,row); 6 used
#define NREP 4                  // accumulator replicas

#define SC_BLOCKS 392           // scatter: (BB*NPIX/4) / 256, 4 px per thread
#define SC_THREADS 256
#define PR_BLOCKS 392           // project: 4 rows per block
#define PR_THREADS 384          // 2 slots x 192 threads; slot handles 2 rows

// Scratch: 4 reps * 1568 rows * 256 B = 1.6 MB. Zero at module load; project
// re-zeroes every word it consumes -> zeroed for the next graph replay.
__device__ float g_acc[(long)NREP * NROWS * ACC_STRIDE];

// ---------------------------------------------------------------------------
__device__ __forceinline__ void red_add_v4(float* addr, float a, float b,
                                           float c, float d) {
    asm volatile("red.global.add.v4.f32 [%0], {%1, %2, %3, %4};"
                 :: "l"(addr), "f"(a), "f"(b), "f"(c), "f"(d) : "memory");
}
__device__ __forceinline__ void red_add_v2(float* addr, float a, float b) {
    asm volatile("red.global.add.v2.f32 [%0], {%1, %2};"
                 :: "l"(addr), "f"(a), "f"(b) : "memory");
}
__device__ __forceinline__ float ld_cg(const float* p) {
    float v;
    asm volatile("ld.global.cg.f32 %0, [%1];" : "=f"(v) : "l"(p));
    return v;
}

// ---------------------------------------------------------------------------
// Kernel A: scatter (proven fastest shape). 4 pixels/thread, LDG.128 input
// loads, 2 vector REDs per pixel. Triggers the dependent project launch as
// soon as its REDs are issued.
// ---------------------------------------------------------------------------
__global__ void __launch_bounds__(SC_THREADS, 8)
scatter_kernel(const float* __restrict__ img,
               const int* __restrict__ seg) {
    int t  = blockIdx.x * SC_THREADS + threadIdx.x;   // one 4-pixel group
    int b  = t / (NPIX / 4);
    int n4 = t - b * (NPIX / 4);
    int n  = n4 * 4;                                  // pixel linear index
    int h  = n / WW;
    int w  = n - h * WW;

    const float4 r4 = *reinterpret_cast<const float4*>(img + ((long)(b * CC + 0) * NPIX + n));
    const float4 g4 = *reinterpret_cast<const float4*>(img + ((long)(b * CC + 1) * NPIX + n));
    const float4 b4 = *reinterpret_cast<const float4*>(img + ((long)(b * CC + 2) * NPIX + n));
    const int4   s4 = *reinterpret_cast<const int4*>(seg + (long)b * NPIX + n);

    const float inv = 1.0f / 223.0f;
    float y = (float)h * inv;

    float rr[4] = {r4.x, r4.y, r4.z, r4.w};
    float gg[4] = {g4.x, g4.y, g4.z, g4.w};
    float bb[4] = {b4.x, b4.y, b4.z, b4.w};
    int   ss[4] = {s4.x, s4.y, s4.z, s4.w};

    float* rep = g_acc + (long)(blockIdx.x & (NREP - 1)) * ((long)NROWS * ACC_STRIDE);

#pragma unroll
    for (int i = 0; i < 4; i++) {
        float x = (float)(w + i) * inv;
        float* base = rep + (long)(b * NSEG + ss[i]) * ACC_STRIDE;
        red_add_v4(base, rr[i], gg[i], bb[i], x);
        red_add_v2(base + 4, y, 1.0f);
    }

    // Let the dependent project kernel begin its prologue now.
    cudaTriggerProgrammaticLaunchCompletion();
}

// ---------------------------------------------------------------------------
// Kernel B: project (PDL secondary). Prologue: load all W/bias float4s into
// registers BEFORE cudaGridDependencySynchronize() — this latency hides under
// the scatter kernel's drain. After the sync: read+reset acc (once per word),
// tiny smem reduce, FMA fan-out, float4 stores.
// ---------------------------------------------------------------------------
__global__ void __launch_bounds__(PR_THREADS, 4)
project_kernel(const float* __restrict__ Wm,
               const float* __restrict__ bias,
               float* __restrict__ out) {
    __shared__ float raw[4][NREP][6];
    __shared__ float sums[4][6];     // per row: r, g, b, x, y, cnt

    const int tid  = threadIdx.x;
    const int row0 = blockIdx.x * 4;
    const int slot = tid / 192;              // 0 or 1
    const int t    = tid - slot * 192;       // 0..191
    const int e    = t * 4;                  // 0..764

    // ---- Prologue (independent of scatter output) ----
    float4 w0 = *reinterpret_cast<const float4*>(Wm + e);
    float4 w1 = *reinterpret_cast<const float4*>(Wm + EE + e);
    float4 w2 = *reinterpret_cast<const float4*>(Wm + 2 * EE + e);
    float4 w3 = *reinterpret_cast<const float4*>(Wm + 3 * EE + e);
    float4 w4 = *reinterpret_cast<const float4*>(Wm + 4 * EE + e);
    float4 bv = *reinterpret_cast<const float4*>(bias + e);

    // ---- Wait for scatter grid completion (memory visible) ----
    cudaGridDependencySynchronize();

    if (tid < 96) {
        int row = tid / 24;
        int l   = tid - row * 24;
        int rep = l / 6;
        int j   = l - rep * 6;
        float* p = g_acc + (long)rep * ((long)NROWS * ACC_STRIDE)
                         + (long)(row0 + row) * ACC_STRIDE + j;
        float v = ld_cg(p);
        *p = 0.0f;                   // reset own word for next replay
        raw[row][rep][j] = v;
    }
    __syncthreads();

    if (tid < 24) {
        int row = tid / 6;
        int j   = tid - row * 6;
        sums[row][j] = raw[row][0][j] + raw[row][1][j]
                     + raw[row][2][j] + raw[row][3][j];
    }
    __syncthreads();

#pragma unroll
    for (int rr = 0; rr < 2; rr++) {
        int row = slot * 2 + rr;
        float cnt = sums[row][5];
        bool  empty = !(cnt > 0.0f);
        float invc  = empty ? 0.0f : (1.0f / cnt);

        float m0 = sums[row][0] * invc;
        float m1 = sums[row][1] * invc;
        float m2 = sums[row][2] * invc;
        float m3 = sums[row][3] * invc;
        float m4 = sums[row][4] * invc;

        float4 r;
        r.x = m0 * w0.x + m1 * w1.x + m2 * w2.x + m3 * w3.x + m4 * w4.x + bv.x;
        r.y = m0 * w0.y + m1 * w1.y + m2 * w2.y + m3 * w3.y + m4 * w4.y + bv.y;
        r.z = m0 * w0.z + m1 * w1.z + m2 * w2.z + m3 * w3.z + m4 * w4.z + bv.z;
        r.w = m0 * w0.w + m1 * w1.w + m2 * w2.w + m3 * w3.w + m4 * w4.w + bv.w;
        if (empty) r = make_float4(0.f, 0.f, 0.f, 0.f);

        *reinterpret_cast<float4*>(out + (long)(row0 + row) * EE + e) = r;
    }
}

// ---------------------------------------------------------------------------
extern "C" void kernel_launch(void* const* d_in, const int* in_sizes, int n_in,
                              void* d_out, int out_size) {
    const float* img  = (const float*)d_in[0];   // [8,3,224,224]
    const int*   seg  = (const int*)d_in[1];     // [8,224,224]
    const float* Wm   = (const float*)d_in[2];   // [5,768]
    const float* bias = (const float*)d_in[3];   // [768]
    float* out = (float*)d_out;                  // [8,196,768]

    (void)in_sizes; (void)n_in; (void)out_size;

    scatter_kernel<<<SC_BLOCKS, SC_THREADS>>>(img, seg);

    // Secondary launch with Programmatic Dependent Launch: may start while
    // scatter is still running; project's cudaGridDependencySynchronize()
    // provides the real dependency.
    cudaLaunchConfig_t cfg = {};
    cfg.gridDim  = dim3(PR_BLOCKS, 1, 1);
    cfg.blockDim = dim3(PR_THREADS, 1, 1);
    cfg.dynamicSmemBytes = 0;
    cudaLaunchAttribute attrs[1];
    attrs[0].id = cudaLaunchAttributeProgrammaticStreamSerialization;
    attrs[0].val.programmaticStreamSerializationAllowed = 1;
    cfg.attrs = attrs;
    cfg.numAttrs = 1;

    cudaError_t err = cudaLaunchKernelEx(&cfg, project_kernel, Wm, bias, out);
    if (err != cudaSuccess) {
        // Fallback: plain stream-ordered launch.
        project_kernel<<<PR_BLOCKS, PR_THREADS>>>(Wm, bias, out);
    }
}